// round 14
// baseline (speedup 1.0000x reference)
#include <cuda_runtime.h>
#include <cuda_fp16.h>
#include <cstdint>

// Problem constants
#define NB    32
#define HIN   64
#define WIN   64
#define T_IN  8
#define A_INP 16
#define T_OUT 8
#define A_OUT 32
#define HC    32
#define WC    32
// 32768 pixels; 1 px/warp, 4 warps/block -> 4 px/block, 8192 blocks

// Permuted fp16 kernel weights, produced once per launch by permute_k_kernel.
// Layout: Kh[ti][p][lane][8] halfs -> one warp-wide LDG.128 = contiguous 512B per (ti,p).
__device__ __align__(16) __half g_Kh[T_IN * 4 * 32 * 8];   // 16 KB

// ---------- packed f32x2 helpers (Blackwell sm_100+) ----------
__device__ __forceinline__ unsigned long long pack2(float lo, float hi) {
    unsigned long long r;
    asm("mov.b64 %0, {%1, %2};" : "=l"(r) : "f"(lo), "f"(hi));
    return r;
}
__device__ __forceinline__ void unpack2(unsigned long long v, float& lo, float& hi) {
    asm("mov.b64 {%0, %1}, %2;" : "=f"(lo), "=f"(hi) : "l"(v));
}
__device__ __forceinline__ unsigned long long ffma2(unsigned long long a,
                                                    unsigned long long b,
                                                    unsigned long long c) {
    unsigned long long d;
    asm("fma.rn.f32x2 %0, %1, %2, %3;" : "=l"(d) : "l"(a), "l"(b), "l"(c));
    return d;
}
__device__ __forceinline__ unsigned long long h2_to_f32x2(unsigned int h2bits) {
    __half2 h;
    *(unsigned int*)&h = h2bits;
    float2 f = __half22float2(h);
    return pack2(f.x, f.y);
}

// dest half-pair index d2 in [0,4096): ti=d2>>9, p=(d2>>7)&3, ln=(d2>>2)&31, cp=d2&3
// source floats (consecutive): ti*1024 + p*256 + (ln>>2)*32 + (ln&3)*8 + 2*cp
__global__ __launch_bounds__(256)
void permute_k_kernel(const float* __restrict__ kern) {
    int d2 = blockIdx.x * 256 + threadIdx.x;
    int ti = d2 >> 9;
    int p  = (d2 >> 7) & 3;
    int ln = (d2 >> 2) & 31;
    int cp = d2 & 3;
    int s = ti * 1024 + p * 256 + (ln >> 2) * 32 + (ln & 3) * 8 + 2 * cp;
    float2 f = *(const float2*)(kern + s);
    ((__half2*)g_Kh)[d2] = __float22half2_rn(f);
}

// Lane mapping in routing: to = lane>>2, q = lane&3; lane owns a=[q*8,q*8+8) of capsule to.
// Routing state split: lane q owns ti in {2q, 2q+1} for softmax/logits.
__global__ __launch_bounds__(128, 4)
void capsule_fused_kernel(const float* __restrict__ x,
                          const float* __restrict__ bias,   // [1][1][8][32]
                          float* __restrict__ out)          // [B][32][32][8][32]
{
    __shared__ __align__(16) float xs_sh[4][T_IN][4];       // [warp][ti][p], 0.5 KB

    const int tid  = threadIdx.x;
    const int warp = tid >> 5;
    const int lane = tid & 31;
    const int gp   = blockIdx.x * 4 + warp;   // this warp's pixel

    // ---------------- Phase 1: coalesced window channel-sums ----------------
    // Instruction p reads region x[b][h(p)][w(p)][:][:] (512B) fully coalesced.
    {
        const int c = lane & 3;      // quarter of the 16-float row
        const int b = gp >> 10;
        const int i = (gp >> 5) & 31;
        const int j = gp & 31;
        float part[4];
#pragma unroll
        for (int p = 0; p < 4; p++) {
            const int h = 2 * i + (p >> 1);
            const int w = 2 * j + (p & 1);
            const float4* rp =
                (const float4*)(x + (((size_t)(b * HIN + h) * WIN + w) * T_IN) * A_INP);
            float4 v = __ldcs(rp + lane);   // streamed once -> evict-first
            part[p] = (v.x + v.y) + (v.z + v.w);
        }
        // quad butterfly: sum the 4 lane-partials of this quad's ti row
#pragma unroll
        for (int p = 0; p < 4; p++) {
            part[p] += __shfl_xor_sync(0xffffffffu, part[p], 1);
            part[p] += __shfl_xor_sync(0xffffffffu, part[p], 2);
        }
        xs_sh[warp][lane >> 2][c] = part[c];   // 128B warp-wide STS
    }
    __syncwarp();

    const int to   = lane >> 2;
    const int q    = lane & 3;
    const int coff = to * 32 + q * 8;   // column offset in [0,256)

    // ---------------- Phase 2: votes, fp16 K via L1-resident LDG ------------
    unsigned long long v2[T_IN][4];
#pragma unroll
    for (int ti = 0; ti < T_IN; ti++) {
        float4 xs = *(const float4*)&xs_sh[warp][ti][0];   // broadcast LDS
        float xp[4] = {xs.x, xs.y, xs.z, xs.w};
        unsigned long long a0, a1, a2, a3;
#pragma unroll
        for (int p = 0; p < 4; p++) {
            // one LDG.128 per (ti,p): lane's 8 fp16 columns, warp-contiguous 512B
            const uint4* kb = (const uint4*)&g_Kh[(ti * 4 + p) * 256 + lane * 8];
            uint4 kh = __ldg(kb);
            unsigned long long K0 = h2_to_f32x2(kh.x);
            unsigned long long K1 = h2_to_f32x2(kh.y);
            unsigned long long K2 = h2_to_f32x2(kh.z);
            unsigned long long K3 = h2_to_f32x2(kh.w);
            unsigned long long sp = pack2(xp[p], xp[p]);
            if (p == 0) {
                a0 = ffma2(sp, K0, 0ull); a1 = ffma2(sp, K1, 0ull);
                a2 = ffma2(sp, K2, 0ull); a3 = ffma2(sp, K3, 0ull);
            } else {
                a0 = ffma2(sp, K0, a0); a1 = ffma2(sp, K1, a1);
                a2 = ffma2(sp, K2, a2); a3 = ffma2(sp, K3, a3);
            }
        }
        v2[ti][0] = a0; v2[ti][1] = a1; v2[ti][2] = a2; v2[ti][3] = a3;
    }

    // bias pairs for this lane's 8 outputs (loop-invariant LDG, L1 hit)
    unsigned long long bias2[4];
    {
        const ulonglong2* bp = (const ulonglong2*)(bias + coff);
        ulonglong2 b0 = __ldg(bp), b1 = __ldg(bp + 1);
        bias2[0] = b0.x; bias2[1] = b0.y; bias2[2] = b1.x; bias2[3] = b1.y;
    }

    const bool hiGroup = (q & 2) != 0;   // group bit (q>>1)
    const bool hiPair  = (q & 1) != 0;   // pair bit (q&1)

    // ---------------- Phase 3: dynamic routing (3 iters) --------------------
    float logit0, logit1;                // logits for ti = 2q, 2q+1 (lane-owned)
    unsigned long long act2[4];
    unsigned long long pre2[4];

    // ---- iteration 0: logits all zero -> route == 1/8 exactly ----
    pre2[0] = bias2[0]; pre2[1] = bias2[1]; pre2[2] = bias2[2]; pre2[3] = bias2[3];
    const unsigned long long c8 = pack2(0.125f, 0.125f);
#pragma unroll
    for (int ti = 0; ti < T_IN; ti++)
#pragma unroll
        for (int k = 0; k < 4; k++) pre2[k] = ffma2(c8, v2[ti][k], pre2[k]);

    {   // squash
        float n2 = 0.0f;
#pragma unroll
        for (int k = 0; k < 4; k++) {
            float lo, hi; unpack2(pre2[k], lo, hi);
            n2 += lo * lo + hi * hi;
        }
        n2 += __shfl_xor_sync(0xffffffffu, n2, 1);
        n2 += __shfl_xor_sync(0xffffffffu, n2, 2);
        float scale = __fdividef(sqrtf(n2), 1.0f + n2);
        unsigned long long sc2 = pack2(scale, scale);
#pragma unroll
        for (int k = 0; k < 4; k++) act2[k] = ffma2(sc2, pre2[k], 0ull);
    }

    // ---- logit-dot + reduce-scatter over the q-quad (lane keeps ti=2q,2q+1) --
    {
        float d[T_IN];
#pragma unroll
        for (int ti = 0; ti < T_IN; ti++) {
            unsigned long long d2;
            d2 = ffma2(v2[ti][0], act2[0], 0ull);
            d2 = ffma2(v2[ti][1], act2[1], d2);
            d2 = ffma2(v2[ti][2], act2[2], d2);
            d2 = ffma2(v2[ti][3], act2[3], d2);
            float lo, hi; unpack2(d2, lo, hi);
            d[ti] = lo + hi;
        }
        // Round 1 (xor 2): send the 4 ti the partner's group owns
        float s0 = hiGroup ? d[0] : d[4];
        float s1 = hiGroup ? d[1] : d[5];
        float s2 = hiGroup ? d[2] : d[6];
        float s3 = hiGroup ? d[3] : d[7];
        float r0 = __shfl_xor_sync(0xffffffffu, s0, 2);
        float r1 = __shfl_xor_sync(0xffffffffu, s1, 2);
        float r2 = __shfl_xor_sync(0xffffffffu, s2, 2);
        float r3 = __shfl_xor_sync(0xffffffffu, s3, 2);
        float m0 = (hiGroup ? d[4] : d[0]) + r0;
        float m1 = (hiGroup ? d[5] : d[1]) + r1;
        float m2 = (hiGroup ? d[6] : d[2]) + r2;
        float m3 = (hiGroup ? d[7] : d[3]) + r3;
        // Round 2 (xor 1): exchange the 2 the partner keeps
        float t0 = hiPair ? m0 : m2;
        float t1 = hiPair ? m1 : m3;
        float u0 = __shfl_xor_sync(0xffffffffu, t0, 1);
        float u1 = __shfl_xor_sync(0xffffffffu, t1, 1);
        logit0 = (hiPair ? m2 : m0) + u0;   // full sum for ti = 2q
        logit1 = (hiPair ? m3 : m1) + u1;   // full sum for ti = 2q+1
    }

    // ---- iterations 1,2: q-parallel softmax (no max-subtraction) ----
#pragma unroll
    for (int r = 1; r < 3; r++) {
        float e0 = __expf(logit0);
        float e1 = __expf(logit1);
        float s0 = e0, s1 = e1;
        s0 += __shfl_xor_sync(0xffffffffu, s0, 4);
        s0 += __shfl_xor_sync(0xffffffffu, s0, 8);
        s0 += __shfl_xor_sync(0xffffffffu, s0, 16);
        s1 += __shfl_xor_sync(0xffffffffu, s1, 4);
        s1 += __shfl_xor_sync(0xffffffffu, s1, 8);
        s1 += __shfl_xor_sync(0xffffffffu, s1, 16);
        float rt0 = __fdividef(e0, s0);    // route[2q][to]
        float rt1 = __fdividef(e1, s1);    // route[2q+1][to]

        pre2[0] = bias2[0]; pre2[1] = bias2[1]; pre2[2] = bias2[2]; pre2[3] = bias2[3];
        // static quad gather: route for absolute ti lives at quad-lane (ti>>1), slot ti&1
#pragma unroll
        for (int ti = 0; ti < T_IN; ti++) {
            float rt = __shfl_sync(0xffffffffu, (ti & 1) ? rt1 : rt0, ti >> 1, 4);
            unsigned long long r2p = pack2(rt, rt);
#pragma unroll
            for (int k = 0; k < 4; k++) pre2[k] = ffma2(r2p, v2[ti][k], pre2[k]);
        }

        float n2 = 0.0f;
#pragma unroll
        for (int k = 0; k < 4; k++) {
            float lo, hi; unpack2(pre2[k], lo, hi);
            n2 += lo * lo + hi * hi;
        }
        n2 += __shfl_xor_sync(0xffffffffu, n2, 1);
        n2 += __shfl_xor_sync(0xffffffffu, n2, 2);
        float scale = __fdividef(sqrtf(n2), 1.0f + n2);
        unsigned long long sc2 = pack2(scale, scale);
#pragma unroll
        for (int k = 0; k < 4; k++) act2[k] = ffma2(sc2, pre2[k], 0ull);

        if (r == 1) {   // final-iteration logit update is dead code
            float d[T_IN];
#pragma unroll
            for (int ti = 0; ti < T_IN; ti++) {
                unsigned long long d2;
                d2 = ffma2(v2[ti][0], act2[0], 0ull);
                d2 = ffma2(v2[ti][1], act2[1], d2);
                d2 = ffma2(v2[ti][2], act2[2], d2);
                d2 = ffma2(v2[ti][3], act2[3], d2);
                float lo, hi; unpack2(d2, lo, hi);
                d[ti] = lo + hi;
            }
            float s0 = hiGroup ? d[0] : d[4];
            float s1 = hiGroup ? d[1] : d[5];
            float s2 = hiGroup ? d[2] : d[6];
            float s3 = hiGroup ? d[3] : d[7];
            float r0 = __shfl_xor_sync(0xffffffffu, s0, 2);
            float r1 = __shfl_xor_sync(0xffffffffu, s1, 2);
            float r2 = __shfl_xor_sync(0xffffffffu, s2, 2);
            float r3 = __shfl_xor_sync(0xffffffffu, s3, 2);
            float m0 = (hiGroup ? d[4] : d[0]) + r0;
            float m1 = (hiGroup ? d[5] : d[1]) + r1;
            float m2 = (hiGroup ? d[6] : d[2]) + r2;
            float m3 = (hiGroup ? d[7] : d[3]) + r3;
            float t0 = hiPair ? m0 : m2;
            float t1 = hiPair ? m1 : m3;
            float u0 = __shfl_xor_sync(0xffffffffu, t0, 1);
            float u1 = __shfl_xor_sync(0xffffffffu, t1, 1);
            logit0 += (hiPair ? m2 : m0) + u0;
            logit1 += (hiPair ? m3 : m1) + u1;
        }
    }

    // ---- Write activation for this pixel ----
    float* op = out + (size_t)gp * (T_OUT * A_OUT) + coff;
    float4 o0, o1;
    unpack2(act2[0], o0.x, o0.y); unpack2(act2[1], o0.z, o0.w);
    unpack2(act2[2], o1.x, o1.y); unpack2(act2[3], o1.z, o1.w);
    ((float4*)op)[0] = o0;
    ((float4*)op)[1] = o1;
}

extern "C" void kernel_launch(void* const* d_in, const int* in_sizes, int n_in,
                              void* d_out, int out_size) {
    const float* x    = (const float*)d_in[0];
    const float* kern = (const float*)d_in[1];
    const float* bias = (const float*)d_in[2];
    float* out = (float*)d_out;
    // 1) permute+convert K weights to fp16 scratch (16 KB), 2) fused capsule kernel
    permute_k_kernel<<<16, 256>>>(kern);
    capsule_fused_kernel<<<8192, 128>>>(x, bias, out);
}

// round 15
// speedup vs baseline: 1.0876x; 1.0876x over previous
#include <cuda_runtime.h>
#include <cuda_fp16.h>
#include <cstdint>

// Problem constants
#define NB    32
#define HIN   64
#define WIN   64
#define T_IN  8
#define A_INP 16
#define T_OUT 8
#define A_OUT 32
#define HC    32
#define WC    32
// 32768 pixels; 2 px/warp, 4 warps/block -> 8 px/block, 4096 blocks

// Permuted fp16 kernel weights, produced once per launch by permute_k_kernel.
// Layout: Kh[ti][p][lane][8] halfs -> one warp-wide LDG.128 = contiguous 512B per (ti,p).
__device__ __align__(16) __half g_Kh[T_IN * 4 * 32 * 8];   // 16 KB

// ---------- packed f32x2 helpers (Blackwell sm_100+) ----------
__device__ __forceinline__ unsigned long long pack2(float lo, float hi) {
    unsigned long long r;
    asm("mov.b64 %0, {%1, %2};" : "=l"(r) : "f"(lo), "f"(hi));
    return r;
}
__device__ __forceinline__ void unpack2(unsigned long long v, float& lo, float& hi) {
    asm("mov.b64 {%0, %1}, %2;" : "=f"(lo), "=f"(hi) : "l"(v));
}
__device__ __forceinline__ unsigned long long ffma2(unsigned long long a,
                                                    unsigned long long b,
                                                    unsigned long long c) {
    unsigned long long d;
    asm("fma.rn.f32x2 %0, %1, %2, %3;" : "=l"(d) : "l"(a), "l"(b), "l"(c));
    return d;
}
__device__ __forceinline__ unsigned long long h2_to_f32x2(unsigned int h2bits) {
    __half2 h;
    *(unsigned int*)&h = h2bits;
    float2 f = __half22float2(h);
    return pack2(f.x, f.y);
}

// dest half-pair index d2 in [0,4096): ti=d2>>9, p=(d2>>7)&3, ln=(d2>>2)&31, cp=d2&3
__global__ __launch_bounds__(256)
void permute_k_kernel(const float* __restrict__ kern) {
    int d2 = blockIdx.x * 256 + threadIdx.x;
    int ti = d2 >> 9;
    int p  = (d2 >> 7) & 3;
    int ln = (d2 >> 2) & 31;
    int cp = d2 & 3;
    int s = ti * 1024 + p * 256 + (ln >> 2) * 32 + (ln & 3) * 8 + 2 * cp;
    float2 f = *(const float2*)(kern + s);
    ((__half2*)g_Kh)[d2] = __float22half2_rn(f);
}

// Lane mapping in routing: to = lane>>2, q = lane&3; lane owns a=[q*8,q*8+8) of capsule to.
// Routing state split: lane q owns ti in {2q, 2q+1} for softmax/logits.
__global__ __launch_bounds__(128, 3)
void capsule_fused_kernel(const float* __restrict__ x,
                          const float* __restrict__ bias,   // [1][1][8][32]
                          float* __restrict__ out)          // [B][32][32][8][32]
{
    __shared__ __align__(16) float xs_sh[4][2][T_IN][4];    // [warp][px][ti][p], 1 KB

    const int tid  = threadIdx.x;
    const int warp = tid >> 5;
    const int lane = tid & 31;
    const int gp0  = blockIdx.x * 8 + warp * 2;   // first pixel of this warp's pair

    // ---------------- Phase 1: coalesced window channel-sums ----------------
    {
        const int tiq = lane >> 2;
        const int c   = lane & 3;
#pragma unroll
        for (int px = 0; px < 2; px++) {
            const int gp = gp0 + px;
            const int b = gp >> 10;
            const int i = (gp >> 5) & 31;
            const int j = gp & 31;
            float part[4];
#pragma unroll
            for (int p = 0; p < 4; p++) {
                const int h = 2 * i + (p >> 1);
                const int w = 2 * j + (p & 1);
                const float4* rp =
                    (const float4*)(x + (((size_t)(b * HIN + h) * WIN + w) * T_IN) * A_INP);
                float4 v = __ldcs(rp + lane);   // streamed once -> evict-first
                part[p] = (v.x + v.y) + (v.z + v.w);
            }
#pragma unroll
            for (int p = 0; p < 4; p++) {
                part[p] += __shfl_xor_sync(0xffffffffu, part[p], 1);
                part[p] += __shfl_xor_sync(0xffffffffu, part[p], 2);
            }
            xs_sh[warp][px][tiq][c] = part[c];   // 128B warp-wide STS
        }
    }
    __syncwarp();

    const int to   = lane >> 2;
    const int q    = lane & 3;
    const int coff = to * 32 + q * 8;   // column offset in [0,256)
    const ulonglong2* bp = (const ulonglong2*)(bias + coff);

    // ---------------- Phase 2: votes for BOTH pixels, fp16 K via L1 LDG ----
    unsigned long long v2[2][T_IN][4];
#pragma unroll
    for (int ti = 0; ti < T_IN; ti++) {
        float4 xsa = *(const float4*)&xs_sh[warp][0][ti][0];   // broadcast LDS
        float4 xsb = *(const float4*)&xs_sh[warp][1][ti][0];
        float xa[4] = {xsa.x, xsa.y, xsa.z, xsa.w};
        float xb[4] = {xsb.x, xsb.y, xsb.z, xsb.w};
        unsigned long long a0, a1, a2, a3, b0_, b1_, b2_, b3_;
#pragma unroll
        for (int p = 0; p < 4; p++) {
            const uint4* kb = (const uint4*)&g_Kh[(ti * 4 + p) * 256 + lane * 8];
            uint4 kh = __ldg(kb);
            unsigned long long K0 = h2_to_f32x2(kh.x);
            unsigned long long K1 = h2_to_f32x2(kh.y);
            unsigned long long K2 = h2_to_f32x2(kh.z);
            unsigned long long K3 = h2_to_f32x2(kh.w);
            unsigned long long sa = pack2(xa[p], xa[p]);
            unsigned long long sb = pack2(xb[p], xb[p]);
            if (p == 0) {
                a0 = ffma2(sa, K0, 0ull); a1 = ffma2(sa, K1, 0ull);
                a2 = ffma2(sa, K2, 0ull); a3 = ffma2(sa, K3, 0ull);
                b0_ = ffma2(sb, K0, 0ull); b1_ = ffma2(sb, K1, 0ull);
                b2_ = ffma2(sb, K2, 0ull); b3_ = ffma2(sb, K3, 0ull);
            } else {
                a0 = ffma2(sa, K0, a0); a1 = ffma2(sa, K1, a1);
                a2 = ffma2(sa, K2, a2); a3 = ffma2(sa, K3, a3);
                b0_ = ffma2(sb, K0, b0_); b1_ = ffma2(sb, K1, b1_);
                b2_ = ffma2(sb, K2, b2_); b3_ = ffma2(sb, K3, b3_);
            }
        }
        v2[0][ti][0] = a0; v2[0][ti][1] = a1; v2[0][ti][2] = a2; v2[0][ti][3] = a3;
        v2[1][ti][0] = b0_; v2[1][ti][1] = b1_; v2[1][ti][2] = b2_; v2[1][ti][3] = b3_;
    }

    const bool hiGroup = (q & 2) != 0;
    const bool hiPair  = (q & 1) != 0;

    // ---------------- Phase 3: routing, both pixels software-pipelined -----
    // Every stage below is a px-pair of INDEPENDENT dependency chains; the
    // scheduler interleaves them, halving exposed exp/shfl/sqrt/div latency.
    float lg0[2], lg1[2];                 // logits for ti = 2q, 2q+1, per px
    unsigned long long act2[2][4];
    unsigned long long pre2[2][4];

    // ---- iteration 0: route == 1/8 exactly; preact both px ----
    const unsigned long long c8 = pack2(0.125f, 0.125f);
#pragma unroll
    for (int px = 0; px < 2; px++) {
        ulonglong2 b0 = __ldg(bp), b1 = __ldg(bp + 1);
        pre2[px][0] = b0.x; pre2[px][1] = b0.y; pre2[px][2] = b1.x; pre2[px][3] = b1.y;
#pragma unroll
        for (int ti = 0; ti < T_IN; ti++)
#pragma unroll
            for (int k = 0; k < 4; k++) pre2[px][k] = ffma2(c8, v2[px][ti][k], pre2[px][k]);
    }
    // squash both px (chains interleave)
#pragma unroll
    for (int px = 0; px < 2; px++) {
        float n2 = 0.0f;
#pragma unroll
        for (int k = 0; k < 4; k++) {
            float lo, hi; unpack2(pre2[px][k], lo, hi);
            n2 += lo * lo + hi * hi;
        }
        n2 += __shfl_xor_sync(0xffffffffu, n2, 1);
        n2 += __shfl_xor_sync(0xffffffffu, n2, 2);
        float scale = __fdividef(sqrtf(n2), 1.0f + n2);
        unsigned long long sc2 = pack2(scale, scale);
#pragma unroll
        for (int k = 0; k < 4; k++) act2[px][k] = ffma2(sc2, pre2[px][k], 0ull);
    }
    // logit-dot + reduce-scatter, both px
#pragma unroll
    for (int px = 0; px < 2; px++) {
        float d[T_IN];
#pragma unroll
        for (int ti = 0; ti < T_IN; ti++) {
            unsigned long long d2;
            d2 = ffma2(v2[px][ti][0], act2[px][0], 0ull);
            d2 = ffma2(v2[px][ti][1], act2[px][1], d2);
            d2 = ffma2(v2[px][ti][2], act2[px][2], d2);
            d2 = ffma2(v2[px][ti][3], act2[px][3], d2);
            float lo, hi; unpack2(d2, lo, hi);
            d[ti] = lo + hi;
        }
        float s0 = hiGroup ? d[0] : d[4];
        float s1 = hiGroup ? d[1] : d[5];
        float s2 = hiGroup ? d[2] : d[6];
        float s3 = hiGroup ? d[3] : d[7];
        float r0 = __shfl_xor_sync(0xffffffffu, s0, 2);
        float r1 = __shfl_xor_sync(0xffffffffu, s1, 2);
        float r2 = __shfl_xor_sync(0xffffffffu, s2, 2);
        float r3 = __shfl_xor_sync(0xffffffffu, s3, 2);
        float m0 = (hiGroup ? d[4] : d[0]) + r0;
        float m1 = (hiGroup ? d[5] : d[1]) + r1;
        float m2 = (hiGroup ? d[6] : d[2]) + r2;
        float m3 = (hiGroup ? d[7] : d[3]) + r3;
        float t0 = hiPair ? m0 : m2;
        float t1 = hiPair ? m1 : m3;
        float u0 = __shfl_xor_sync(0xffffffffu, t0, 1);
        float u1 = __shfl_xor_sync(0xffffffffu, t1, 1);
        lg0[px] = (hiPair ? m2 : m0) + u0;
        lg1[px] = (hiPair ? m3 : m1) + u1;
    }

    // ---- iterations 1,2 ----
#pragma unroll
    for (int r = 1; r < 3; r++) {
        float rt0[2], rt1[2];
        // softmax both px (chains interleave)
#pragma unroll
        for (int px = 0; px < 2; px++) {
            float e0 = __expf(lg0[px]);
            float e1 = __expf(lg1[px]);
            float s0 = e0, s1 = e1;
            s0 += __shfl_xor_sync(0xffffffffu, s0, 4);
            s0 += __shfl_xor_sync(0xffffffffu, s0, 8);
            s0 += __shfl_xor_sync(0xffffffffu, s0, 16);
            s1 += __shfl_xor_sync(0xffffffffu, s1, 4);
            s1 += __shfl_xor_sync(0xffffffffu, s1, 8);
            s1 += __shfl_xor_sync(0xffffffffu, s1, 16);
            rt0[px] = __fdividef(e0, s0);
            rt1[px] = __fdividef(e1, s1);
        }
        // preact both px
#pragma unroll
        for (int px = 0; px < 2; px++) {
            ulonglong2 b0 = __ldg(bp), b1 = __ldg(bp + 1);
            pre2[px][0] = b0.x; pre2[px][1] = b0.y; pre2[px][2] = b1.x; pre2[px][3] = b1.y;
#pragma unroll
            for (int ti = 0; ti < T_IN; ti++) {
                float rt = __shfl_sync(0xffffffffu, (ti & 1) ? rt1[px] : rt0[px], ti >> 1, 4);
                unsigned long long r2p = pack2(rt, rt);
#pragma unroll
                for (int k = 0; k < 4; k++) pre2[px][k] = ffma2(r2p, v2[px][ti][k], pre2[px][k]);
            }
        }
        // squash both px
#pragma unroll
        for (int px = 0; px < 2; px++) {
            float n2 = 0.0f;
#pragma unroll
            for (int k = 0; k < 4; k++) {
                float lo, hi; unpack2(pre2[px][k], lo, hi);
                n2 += lo * lo + hi * hi;
            }
            n2 += __shfl_xor_sync(0xffffffffu, n2, 1);
            n2 += __shfl_xor_sync(0xffffffffu, n2, 2);
            float scale = __fdividef(sqrtf(n2), 1.0f + n2);
            unsigned long long sc2 = pack2(scale, scale);
#pragma unroll
            for (int k = 0; k < 4; k++) act2[px][k] = ffma2(sc2, pre2[px][k], 0ull);
        }
        // logit update (dead on final iteration)
        if (r == 1) {
#pragma unroll
            for (int px = 0; px < 2; px++) {
                float d[T_IN];
#pragma unroll
                for (int ti = 0; ti < T_IN; ti++) {
                    unsigned long long d2;
                    d2 = ffma2(v2[px][ti][0], act2[px][0], 0ull);
                    d2 = ffma2(v2[px][ti][1], act2[px][1], d2);
                    d2 = ffma2(v2[px][ti][2], act2[px][2], d2);
                    d2 = ffma2(v2[px][ti][3], act2[px][3], d2);
                    float lo, hi; unpack2(d2, lo, hi);
                    d[ti] = lo + hi;
                }
                float s0 = hiGroup ? d[0] : d[4];
                float s1 = hiGroup ? d[1] : d[5];
                float s2 = hiGroup ? d[2] : d[6];
                float s3 = hiGroup ? d[3] : d[7];
                float r0 = __shfl_xor_sync(0xffffffffu, s0, 2);
                float r1 = __shfl_xor_sync(0xffffffffu, s1, 2);
                float r2 = __shfl_xor_sync(0xffffffffu, s2, 2);
                float r3 = __shfl_xor_sync(0xffffffffu, s3, 2);
                float m0 = (hiGroup ? d[4] : d[0]) + r0;
                float m1 = (hiGroup ? d[5] : d[1]) + r1;
                float m2 = (hiGroup ? d[6] : d[2]) + r2;
                float m3 = (hiGroup ? d[7] : d[3]) + r3;
                float t0 = hiPair ? m0 : m2;
                float t1 = hiPair ? m1 : m3;
                float u0 = __shfl_xor_sync(0xffffffffu, t0, 1);
                float u1 = __shfl_xor_sync(0xffffffffu, t1, 1);
                lg0[px] += (hiPair ? m2 : m0) + u0;
                lg1[px] += (hiPair ? m3 : m1) + u1;
            }
        }
    }

    // ---- Write activations ----
#pragma unroll
    for (int px = 0; px < 2; px++) {
        const int gp = gp0 + px;
        float* op = out + (size_t)gp * (T_OUT * A_OUT) + coff;
        float4 o0, o1;
        unpack2(act2[px][0], o0.x, o0.y); unpack2(act2[px][1], o0.z, o0.w);
        unpack2(act2[px][2], o1.x, o1.y); unpack2(act2[px][3], o1.z, o1.w);
        ((float4*)op)[0] = o0;
        ((float4*)op)[1] = o1;
    }
}

extern "C" void kernel_launch(void* const* d_in, const int* in_sizes, int n_in,
                              void* d_out, int out_size) {
    const float* x    = (const float*)d_in[0];
    const float* kern = (const float*)d_in[1];
    const float* bias = (const float*)d_in[2];
    float* out = (float*)d_out;
    // 1) permute+convert K weights to fp16 scratch (16 KB), 2) fused capsule kernel
    permute_k_kernel<<<16, 256>>>(kern);
    capsule_fused_kernel<<<4096, 128>>>(x, bias, out);
}